// round 4
// baseline (speedup 1.0000x reference)
#include <cuda_runtime.h>
#include <cstdint>

#define NC    192
#define HW    56
#define PLANE (HW*HW)
#define KK    49
#define TILE_ROWS 28
#define IN_ROWS   34          // TILE_ROWS + 6
#define SH_W      62          // 56 + 6 halo
#define NT        224         // 4 row-groups x 56 cols

typedef unsigned long long u64;

__device__ __forceinline__ u64 pack2(float lo, float hi) {
    return (u64)__float_as_uint(lo) | ((u64)__float_as_uint(hi) << 32);
}

__device__ __forceinline__ u64 ffma2(u64 a, u64 b, u64 c) {
    u64 d;
    asm("fma.rn.f32x2 %0, %1, %2, %3;" : "=l"(d) : "l"(a), "l"(b), "l"(c));
    return d;
}

// mantissa_map: a = |v|+1e-7 (always normal); m = mantissa(a) in [1,2);
// M = m>=1.5 ? m/2 : m   (matches reference incl. its log2-rounding wraparound)
__device__ __forceinline__ float mant_map(float v) {
    float a = fabsf(v) + 1e-7f;
    unsigned u = __float_as_uint(a);
    float m = __uint_as_float((u & 0x007FFFFFu) | 0x3F800000u);
    return (m >= 1.5f) ? m * 0.5f : m;
}

__global__ void __launch_bounds__(NT, 2)
appro_waconv_kernel(const float* __restrict__ x,
                    const float* __restrict__ w,
                    float* __restrict__ out)
{
    __shared__ u64 sh[IN_ROWS * SH_W];   // (x, x/M1) packed, zero halo
    __shared__ u64 shw[KK];              // (A, w-A) packed

    const int plane = blockIdx.y;              // b*NC + c
    const int tile  = blockIdx.x;              // 0..1 (28-row tiles)
    const int c     = plane % NC;
    const int tid   = threadIdx.x;             // 0..223

    const float* __restrict__ xin = x + (size_t)plane * PLANE;

    // --- weights: A = w/M2, B = w - A (49 taps, this channel) ---
    if (tid < KK) {
        float wv = w[c * KK + tid];
        float M2 = mant_map(wv);
        float A  = wv / M2;
        shw[tid] = pack2(A, wv - A);
    }

    // --- input halo tile: packed (x, x/M1); zeros in the 3-wide pad ---
    const int row0 = tile * TILE_ROWS - 3;     // first input row (global)
    for (int cell = tid; cell < IN_ROWS * SH_W; cell += NT) {
        int hy = cell / SH_W;
        int hx = cell - hy * SH_W;
        int iy = row0 + hy, ix = hx - 3;
        u64 v = 0ull;
        if ((unsigned)iy < (unsigned)HW && (unsigned)ix < (unsigned)HW) {
            float xv = __ldg(&xin[iy * HW + ix]);
            float M1 = mant_map(xv);
            v = pack2(xv, __fdividef(xv, M1));
        }
        sh[cell] = v;
    }
    __syncthreads();

    // weights into registers (broadcast LDS, one-time, must stay resident)
    u64 wr[KK];
#pragma unroll
    for (int i = 0; i < KK; ++i) wr[i] = shw[i];

    const int ty  = tid / 56;                  // 0..3  (7 output rows each)
    const int col = tid - ty * 56;             // 0..55

    u64 acc[7];
#pragma unroll
    for (int i = 0; i < 7; ++i) acc[i] = 0ull;

    const u64* __restrict__ base = &sh[(ty * 7) * SH_W + col];

    // sliding-row reuse: 13 input rows feed 7 output rows
#pragma unroll
    for (int r = 0; r < 13; ++r) {
        u64 p[7];
#pragma unroll
        for (int j = 0; j < 7; ++j) p[j] = base[r * SH_W + j];
#pragma unroll
        for (int k = 0; k < 7; ++k) {
            const int i = r - k;
            if (i >= 0 && i < 7) {
#pragma unroll
                for (int j = 0; j < 7; ++j)
                    acc[i] = ffma2(p[j], wr[k * 7 + j], acc[i]);
            }
        }
    }

    float* __restrict__ o = out + (size_t)plane * PLANE
                          + (tile * TILE_ROWS + ty * 7) * HW + col;
#pragma unroll
    for (int i = 0; i < 7; ++i) {
        float lo = __uint_as_float((unsigned)(acc[i] & 0xFFFFFFFFull));
        float hi = __uint_as_float((unsigned)(acc[i] >> 32));
        o[i * HW] = lo + hi;
    }
}

extern "C" void kernel_launch(void* const* d_in, const int* in_sizes, int n_in,
                              void* d_out, int out_size)
{
    const float* x = (const float*)d_in[0];      // (4,192,56,56) fp32
    const float* w = (const float*)d_in[1];      // (192,1,7,7)   fp32
    float* out = (float*)d_out;                  // (4,192,56,56) fp32

    dim3 block(NT);
    dim3 grid(2, 4 * NC);                        // 2 row-tiles x 768 planes
    appro_waconv_kernel<<<grid, block>>>(x, w, out);
}

// round 5
// speedup vs baseline: 1.2396x; 1.2396x over previous
#include <cuda_runtime.h>
#include <cstdint>

#define NC    192
#define HW    56
#define PLANE (HW*HW)
#define KK    49
#define SH_W  62
#define NT    224            // 28 row-groups (R=2) x 8 col-groups (C=7)

typedef unsigned long long u64;

__device__ __forceinline__ u64 pack2(float lo, float hi) {
    return (u64)__float_as_uint(lo) | ((u64)__float_as_uint(hi) << 32);
}

__device__ __forceinline__ u64 ffma2(u64 a, u64 b, u64 c) {
    u64 d;
    asm("fma.rn.f32x2 %0, %1, %2, %3;" : "=l"(d) : "l"(a), "l"(b), "l"(c));
    return d;
}

// mantissa_map: a = |v|+1e-7 (always normal); m = mantissa(a) in [1,2);
// M = m>=1.5 ? m/2 : m   (== reference piecewise map, values in [0.75,1.5))
__device__ __forceinline__ float mant_map(float v) {
    float a = fabsf(v) + 1e-7f;
    unsigned u = __float_as_uint(a);
    float m = __uint_as_float((u & 0x007FFFFFu) | 0x3F800000u);
    return (m >= 1.5f) ? m * 0.5f : m;
}

__global__ void __launch_bounds__(NT, 3)
appro_waconv_kernel(const float* __restrict__ x,
                    const float* __restrict__ w,
                    float* __restrict__ out)
{
    __shared__ u64 sh[SH_W * SH_W];   // (x, x/M1) packed, zero halo (row 0 = global row -3)
    __shared__ u64 shw[KK];           // (A, w-A) packed

    const int plane = blockIdx.x;            // b*NC + c : one full 56x56 plane
    const int c     = plane % NC;
    const int tid   = threadIdx.x;           // 0..223

    const float* __restrict__ xin = x + (size_t)plane * PLANE;

    // --- weights: A = w/M2, B = w - A ---
    if (tid < KK) {
        float wv = w[c * KK + tid];
        float M2 = mant_map(wv);
        float A  = wv / M2;
        shw[tid] = pack2(A, wv - A);
    }

    // --- input halo tile: packed (x, x/M1); zeros in the 3-wide pad ---
    for (int cell = tid; cell < SH_W * SH_W; cell += NT) {
        int hy = cell / SH_W;
        int hx = cell - hy * SH_W;
        int iy = hy - 3, ix = hx - 3;
        u64 v = 0ull;
        if ((unsigned)iy < (unsigned)HW && (unsigned)ix < (unsigned)HW) {
            float xv = __ldg(&xin[iy * HW + ix]);
            float M1 = mant_map(xv);
            v = pack2(xv, __fdividef(xv, M1));
        }
        sh[cell] = v;
    }
    __syncthreads();

    const int cg = tid & 7;                  // col group: cols [cg*7, cg*7+7)
    const int rg = tid >> 3;                 // row group: rows {rg*2, rg*2+1}

    u64 acc[2][7];
#pragma unroll
    for (int o = 0; o < 2; ++o)
#pragma unroll
        for (int cc = 0; cc < 7; ++cc) acc[o][cc] = 0ull;

    const u64* __restrict__ base = &sh[(rg * 2) * SH_W + cg * 7];

    // 8 input rows feed 2 output rows; 13-wide pixel window slides in registers
#pragma unroll
    for (int r = 0; r < 8; ++r) {
        u64 p[13];
#pragma unroll
        for (int m = 0; m < 13; ++m) p[m] = base[r * SH_W + m];
#pragma unroll
        for (int o = 0; o < 2; ++o) {
            const int k = r - o;
            if (k >= 0 && k < 7) {
#pragma unroll
                for (int j = 0; j < 7; ++j) {
                    const u64 wv = shw[k * 7 + j];   // broadcast, reused 7x in regs
#pragma unroll
                    for (int cc = 0; cc < 7; ++cc)
                        acc[o][cc] = ffma2(p[cc + j], wv, acc[o][cc]);
                }
            }
        }
    }

    // --- stage outputs in smem for coalesced global stores ---
    __syncthreads();                          // everyone done reading sh
    float* shf = (float*)sh;
#pragma unroll
    for (int o = 0; o < 2; ++o)
#pragma unroll
        for (int cc = 0; cc < 7; ++cc) {
            float lo = __uint_as_float((unsigned)(acc[o][cc] & 0xFFFFFFFFull));
            float hi = __uint_as_float((unsigned)(acc[o][cc] >> 32));
            shf[(rg * 2 + o) * HW + cg * 7 + cc] = lo + hi;
        }
    __syncthreads();

    float* __restrict__ o = out + (size_t)plane * PLANE;
#pragma unroll
    for (int i = tid; i < PLANE; i += NT)     // 14 fully-coalesced STG.32
        o[i] = shf[i];
}

extern "C" void kernel_launch(void* const* d_in, const int* in_sizes, int n_in,
                              void* d_out, int out_size)
{
    const float* x = (const float*)d_in[0];      // (4,192,56,56) fp32
    const float* w = (const float*)d_in[1];      // (192,1,7,7)   fp32
    float* out = (float*)d_out;                  // (4,192,56,56) fp32

    appro_waconv_kernel<<<4 * NC, NT>>>(x, w, out);
}